// round 15
// baseline (speedup 1.0000x reference)
#include <cuda_runtime.h>
#include <math_constants.h>

// SPP: out = concat([x, maxpool5(x), maxpool9(x), maxpool13(x)], axis=C)
// x: (16, 512, 64, 64) f32 ; out: (16, 2048, 64, 64) f32
// SPPF identity: pool9 = pool5(pool5(x)), pool13 = pool5(pool9).
// Separable 5x5 pools; thread owns one float4-column x 4 rows in registers.
// Horizontal pass via warp shuffles; shared memory only for the 4-row
// vertical halo, PING-PONGED across pools so each pool needs one barrier.

#define NCH 512
#define HW  64
#define PLANE 4096          // 64*64 floats
#define PLANE4 1024         // in float4 units
#define ROW4 16             // float4s per row

__device__ __forceinline__ float4 f4max(float4 a, float4 b) {
    return make_float4(fmaxf(a.x, b.x), fmaxf(a.y, b.y),
                       fmaxf(a.z, b.z), fmaxf(a.w, b.w));
}

__global__ __launch_bounds__(256, 5)
void spp_kernel(const float* __restrict__ x, float* __restrict__ out) {
    __shared__ float4 sB[2][PLANE4];   // ping-pong h-field (halo exchange)

    const int tid   = threadIdx.x;
    const int col4  = tid & (ROW4 - 1);     // 0..15
    const int rb    = (tid >> 4) << 2;      // row base: 0,4,...,60
    const int plane = blockIdx.x;           // n*512 + c
    const int n     = plane >> 9;
    const int c     = plane & 511;

    const float4 NEG4 = make_float4(-CUDART_INF_F, -CUDART_INF_F,
                                    -CUDART_INF_F, -CUDART_INF_F);
    const unsigned FULL = 0xffffffffu;

    const float4* __restrict__ xp4 =
        (const float4*)(x + (size_t)plane * PLANE);
    float4* out0 = (float4*)(out + ((size_t)(n * 2048 + c)) * PLANE);

    const int g0 = rb * ROW4 + col4;

    // ---- load plane into registers + passthrough copy (chunk 0) ----
    float4 v[4];
    #pragma unroll
    for (int i = 0; i < 4; i++) {
        v[i] = __ldcs(&xp4[g0 + i * ROW4]);
        __stcs(&out0[g0 + i * ROW4], v[i]);
    }

    // ---- chain of three 5x5 pools ----
    #pragma unroll
    for (int j = 1; j <= 3; j++) {
        float4* sb = sB[j & 1];

        // horizontal window-5 max via warp shuffle: v[] -> hv[] (registers)
        float4 hv[4];
        #pragma unroll
        for (int i = 0; i < 4; i++) {
            float4 m = v[i];
            float lz = __shfl_up_sync(FULL, m.z, 1);
            float lw = __shfl_up_sync(FULL, m.w, 1);
            float rx = __shfl_down_sync(FULL, m.x, 1);
            float ry = __shfl_down_sync(FULL, m.y, 1);
            if (col4 == 0)        { lz = -CUDART_INF_F; lw = -CUDART_INF_F; }
            if (col4 == ROW4 - 1) { rx = -CUDART_INF_F; ry = -CUDART_INF_F; }

            const float p12 = fmaxf(m.y, m.z);
            hv[i].x = fmaxf(fmaxf(lz, lw),  fmaxf(m.x, p12));
            hv[i].y = fmaxf(fmaxf(lw, m.x), fmaxf(p12, m.w));
            hv[i].z = fmaxf(fmaxf(m.x, p12), fmaxf(m.w, rx));
            hv[i].w = fmaxf(fmaxf(p12, m.w), fmaxf(rx,  ry));
        }

        // publish h-field for vertical halo (ping-pong: no trailing sync
        // needed — the next pool writes the other buffer, and the pool
        // after that is ordered through the intervening barrier)
        #pragma unroll
        for (int i = 0; i < 4; i++) sb[g0 + i * ROW4] = hv[i];
        __syncthreads();

        // vertical window-5 max: registers + 4-row halo from shared
        float4 vv0, vv1, vv6, vv7;
        if (rb > 0) {
            vv0 = sb[g0 - 2 * ROW4];
            vv1 = sb[g0 - 1 * ROW4];
        } else { vv0 = NEG4; vv1 = NEG4; }
        if (rb < HW - 4) {
            vv6 = sb[g0 + 4 * ROW4];
            vv7 = sb[g0 + 5 * ROW4];
        } else { vv6 = NEG4; vv7 = NEG4; }

        float4 p0 = f4max(vv0,   vv1);
        float4 p1 = f4max(vv1,   hv[0]);
        float4 p2 = f4max(hv[0], hv[1]);
        float4 p3 = f4max(hv[1], hv[2]);
        float4 p4 = f4max(hv[2], hv[3]);
        float4 p5 = f4max(hv[3], vv6);

        v[0] = f4max(f4max(p0, p2), hv[2]);
        v[1] = f4max(f4max(p1, p3), hv[3]);
        v[2] = f4max(f4max(p2, p4), vv6);
        v[3] = f4max(f4max(p3, p5), vv7);

        float4* outj = (float4*)(out + ((size_t)(n * 2048 + j * 512 + c)) * PLANE);
        #pragma unroll
        for (int i = 0; i < 4; i++) __stcs(&outj[g0 + i * ROW4], v[i]);
    }
}

extern "C" void kernel_launch(void* const* d_in, const int* in_sizes, int n_in,
                              void* d_out, int out_size) {
    const float* x = (const float*)d_in[0];
    float* out = (float*)d_out;
    spp_kernel<<<16 * NCH, 256>>>(x, out);
}

// round 16
// speedup vs baseline: 1.0401x; 1.0401x over previous
#include <cuda_runtime.h>
#include <math_constants.h>

// SPP: out = concat([x, maxpool5(x), maxpool9(x), maxpool13(x)], axis=C)
// x: (16, 512, 64, 64) f32 ; out: (16, 2048, 64, 64) f32
// SPPF identity: pool9 = pool5(pool5(x)), pool13 = pool5(pool9).
// Separable 5x5 pools; thread owns one float4-column x 4 rows in registers.
// Horizontal pass via warp shuffles; shared memory only for the 4-row
// vertical halo. TWO planes per CTA, interleaved per-thread, to double
// memory-level parallelism and halve barrier overhead per byte.

#define NCH 512
#define HW  64
#define PLANE 4096          // 64*64 floats
#define PLANE4 1024         // in float4 units
#define ROW4 16             // float4s per row

__device__ __forceinline__ float4 f4max(float4 a, float4 b) {
    return make_float4(fmaxf(a.x, b.x), fmaxf(a.y, b.y),
                       fmaxf(a.z, b.z), fmaxf(a.w, b.w));
}

// horizontal window-5 max on one row's float4 via lane +-1 shuffles
__device__ __forceinline__ float4 hpass(float4 m, int col4) {
    const unsigned FULL = 0xffffffffu;
    float lz = __shfl_up_sync(FULL, m.z, 1);
    float lw = __shfl_up_sync(FULL, m.w, 1);
    float rx = __shfl_down_sync(FULL, m.x, 1);
    float ry = __shfl_down_sync(FULL, m.y, 1);
    if (col4 == 0)        { lz = -CUDART_INF_F; lw = -CUDART_INF_F; }
    if (col4 == ROW4 - 1) { rx = -CUDART_INF_F; ry = -CUDART_INF_F; }
    const float p12 = fmaxf(m.y, m.z);
    float4 o;
    o.x = fmaxf(fmaxf(lz, lw),  fmaxf(m.x, p12));
    o.y = fmaxf(fmaxf(lw, m.x), fmaxf(p12, m.w));
    o.z = fmaxf(fmaxf(m.x, p12), fmaxf(m.w, rx));
    o.w = fmaxf(fmaxf(p12, m.w), fmaxf(rx,  ry));
    return o;
}

// vertical window-5 max: own 4 h-rows in registers + 4-row halo from shared
__device__ __forceinline__ void vpass(const float4* __restrict__ sb,
                                      const float4 hv[4], float4 v[4],
                                      int g0, int rb) {
    const float4 NEG4 = make_float4(-CUDART_INF_F, -CUDART_INF_F,
                                    -CUDART_INF_F, -CUDART_INF_F);
    float4 vv0, vv1, vv6, vv7;
    if (rb > 0) {
        vv0 = sb[g0 - 2 * ROW4];
        vv1 = sb[g0 - 1 * ROW4];
    } else { vv0 = NEG4; vv1 = NEG4; }
    if (rb < HW - 4) {
        vv6 = sb[g0 + 4 * ROW4];
        vv7 = sb[g0 + 5 * ROW4];
    } else { vv6 = NEG4; vv7 = NEG4; }

    float4 p0 = f4max(vv0,   vv1);
    float4 p1 = f4max(vv1,   hv[0]);
    float4 p2 = f4max(hv[0], hv[1]);
    float4 p3 = f4max(hv[1], hv[2]);
    float4 p4 = f4max(hv[2], hv[3]);
    float4 p5 = f4max(hv[3], vv6);

    v[0] = f4max(f4max(p0, p2), hv[2]);
    v[1] = f4max(f4max(p1, p3), hv[3]);
    v[2] = f4max(f4max(p2, p4), vv6);
    v[3] = f4max(f4max(p3, p5), vv7);
}

__global__ __launch_bounds__(256, 3)
void spp_kernel(const float* __restrict__ x, float* __restrict__ out) {
    __shared__ float4 sb[2][PLANE4];   // one halo buffer per plane

    const int tid   = threadIdx.x;
    const int col4  = tid & (ROW4 - 1);     // 0..15
    const int rb    = (tid >> 4) << 2;      // row base: 0,4,...,60
    const int g0    = rb * ROW4 + col4;

    const int pa = blockIdx.x * 2;          // plane a: n*512 + c
    const int pb = pa + 1;
    const int na = pa >> 9, ca = pa & 511;
    const int nb = pb >> 9, cb = pb & 511;

    const float4* __restrict__ xa4 = (const float4*)(x + (size_t)pa * PLANE);
    const float4* __restrict__ xb4 = (const float4*)(x + (size_t)pb * PLANE);
    float4* outa0 = (float4*)(out + ((size_t)(na * 2048 + ca)) * PLANE);
    float4* outb0 = (float4*)(out + ((size_t)(nb * 2048 + cb)) * PLANE);

    // ---- load both planes into registers (8 independent LDG.128) ----
    float4 va[4], vb[4];
    #pragma unroll
    for (int i = 0; i < 4; i++) va[i] = xa4[g0 + i * ROW4];
    #pragma unroll
    for (int i = 0; i < 4; i++) vb[i] = xb4[g0 + i * ROW4];

    // passthrough copies (chunk 0)
    #pragma unroll
    for (int i = 0; i < 4; i++) outa0[g0 + i * ROW4] = va[i];
    #pragma unroll
    for (int i = 0; i < 4; i++) outb0[g0 + i * ROW4] = vb[i];

    // ---- chain of three 5x5 pools on both planes ----
    #pragma unroll
    for (int j = 1; j <= 3; j++) {
        // horizontal pass, both planes (registers only)
        float4 hva[4], hvb[4];
        #pragma unroll
        for (int i = 0; i < 4; i++) hva[i] = hpass(va[i], col4);
        #pragma unroll
        for (int i = 0; i < 4; i++) hvb[i] = hpass(vb[i], col4);

        // publish h-fields for the vertical halo
        #pragma unroll
        for (int i = 0; i < 4; i++) sb[0][g0 + i * ROW4] = hva[i];
        #pragma unroll
        for (int i = 0; i < 4; i++) sb[1][g0 + i * ROW4] = hvb[i];
        __syncthreads();

        // vertical pass, both planes
        vpass(sb[0], hva, va, g0, rb);
        vpass(sb[1], hvb, vb, g0, rb);

        float4* outaj = (float4*)(out + ((size_t)(na * 2048 + j * 512 + ca)) * PLANE);
        float4* outbj = (float4*)(out + ((size_t)(nb * 2048 + j * 512 + cb)) * PLANE);
        #pragma unroll
        for (int i = 0; i < 4; i++) outaj[g0 + i * ROW4] = va[i];
        #pragma unroll
        for (int i = 0; i < 4; i++) outbj[g0 + i * ROW4] = vb[i];

        // halo readers must finish before next pool overwrites sb
        if (j != 3) __syncthreads();
    }
}

extern "C" void kernel_launch(void* const* d_in, const int* in_sizes, int n_in,
                              void* d_out, int out_size) {
    const float* x = (const float*)d_in[0];
    float* out = (float*)d_out;
    spp_kernel<<<16 * NCH / 2, 256>>>(x, out);
}